// round 12
// baseline (speedup 1.0000x reference)
#include <cuda_runtime.h>
#include <cstdint>

typedef unsigned long long u64;
typedef unsigned u32;

#define N13   16224
#define N26   64896
#define N52   259584
#define NT    340704
#define CAP   4096
#define NK    512
#define HB    4096
#define GRID  148
#define BLK   1024
#define NTH   (GRID*BLK)

#define G26OFF 16224
#define G52OFF 81120

#define W52 64896
#define W26 16224
#define W13 16224
#define WTOT 97344

// ---------------- scratch (static device globals: no allocation) ------------
__device__ u64   g_keys[NT];
__device__ u32   g_hist[HB];
__device__ u32   g_cnt;
__device__ u32   g_maxfs;
__device__ u64   g_gbuf[CAP];
__device__ float g_cand[NK * 6];
__device__ unsigned char g_alive[NK];
__device__ u32   g_bar_arrive;
__device__ u32   g_bar_gen;

__device__ __forceinline__ u32 fordf(float f) {
    u32 u = __float_as_uint(f);
    return (u & 0x80000000u) ? ~u : (u | 0x80000000u);
}
__device__ __forceinline__ float ifordf(u32 e) {
    return __uint_as_float((e & 0x80000000u) ? (e & 0x7fffffffu) : ~e);
}

// grid barrier: exactly one block per SM (GRID=148, launch_bounds(1024,1))
__device__ __forceinline__ void grid_barrier() {
    __syncthreads();
    __threadfence();
    if (threadIdx.x == 0) {
        volatile u32* vgen = &g_bar_gen;
        u32 gen = *vgen;
        __threadfence();
        u32 a = atomicAdd(&g_bar_arrive, 1u);
        if (a == GRID - 1u) {
            g_bar_arrive = 0u;
            __threadfence();
            atomicAdd(&g_bar_gen, 1u);
        } else {
            while (*vgen == gen) {}
        }
    }
    __threadfence();
    __syncthreads();
}

// map candidate id -> (S, src, anc, a, b, cell)
__device__ __forceinline__ void map_id(u32 id,
    const float* o13, const float* o26, const float* o52,
    const float* a13, const float* a26, const float* a52,
    int& S, const float*& src, const float*& anc, int& a, int& b, int& cell) {
    u32 rid = id;
    if (id < N13)            { S = 13; src = o13; anc = a13; }
    else if (id < N13 + N26) { S = 26; src = o26; anc = a26; rid = id - N13; }
    else                     { S = 52; src = o52; anc = a52; rid = id - (N13 + N26); }
    a = rid % 3;
    u32 q = rid / 3;
    int SS = S * S;
    b = q / SS;
    cell = q - b * SS;
}

// ---------------- decode: score-only, vec4, precise expf ---------------------
template <int S, int GOFF>
__device__ __forceinline__ void decode_v4(int v,
                                          const float* __restrict__ out,
                                          u32* shist) {
    const int SS = S * S, G4 = SS / 4;
    int plane = v / G4;
    int grp = v - plane * G4;
    int cell0 = grp * 4;
    int b = plane / 3, a = plane - 3 * b;
    const float* pc = out + ((size_t)b * 255 + (size_t)a * 85) * SS + cell0;
    float4 q0 = *(const float4*)pc;
    float m0 = -1e30f, m1 = -1e30f, m2 = -1e30f, m3 = -1e30f;
    float s0 = 0.f, s1 = 0.f, s2 = 0.f, s3 = 0.f;
    int i0 = 0, i1 = 0, i2 = 0, i3 = 0;
#pragma unroll 4
    for (int c = 0; c < 80; ++c) {
        float4 l = *(const float4*)(pc + (size_t)(5 + c) * SS);
        s0 += expf(l.x); if (l.x > m0) { m0 = l.x; i0 = c; }
        s1 += expf(l.y); if (l.y > m1) { m1 = l.y; i1 = c; }
        s2 += expf(l.z); if (l.z > m2) { m2 = l.z; i2 = c; }
        s3 += expf(l.w); if (l.w > m3) { m3 = l.w; i3 = c; }
    }
    float o0a[4] = {q0.x, q0.y, q0.z, q0.w};
    float ma[4] = {m0, m1, m2, m3};
    float sa[4] = {s0, s1, s2, s3};
    int   ia[4] = {i0, i1, i2, i3};
#pragma unroll
    for (int k = 0; k < 4; ++k) {
        int cell = cell0 + k;
        u32 g = (u32)(GOFF + (b * SS + cell) * 3 + a);
        float score = -1.f;
        if (o0a[k] > 0.f) {
            float obj = 1.f / (1.f + expf(-o0a[k]));
            score = obj * expf(ma[k]) / sa[k];
        }
        u32 fs = fordf(score);
        g_keys[GOFF + plane * SS + cell] =
            ((u64)fs << 32) | (u32)(~((g << 7) | (u32)ia[k]));
        if (fs > 0x80000000u) atomicAdd(&shist[(fs >> 18) - 8192u], 1u);
    }
}

__device__ __forceinline__ void decode_s13(int v,
                                           const float* __restrict__ out,
                                           u32* shist) {
    const int S = 13, SS = 169;
    int plane = v / SS;
    int cell = v - plane * SS;
    int b = plane / 3, a = plane - 3 * b;
    const float* pc = out + ((size_t)b * 255 + (size_t)a * 85) * SS + cell;
    float o0 = pc[0];
    u32 g = (u32)((b * SS + cell) * 3 + a);
    float score = -1.f;
    float m = -1e30f, sum = 0.f; int am = 0;
#pragma unroll 4
    for (int c = 0; c < 80; ++c) {
        float l = pc[(size_t)(5 + c) * SS];
        sum += expf(l);
        if (l > m) { m = l; am = c; }
    }
    if (o0 > 0.f) {
        float obj = 1.f / (1.f + expf(-o0));
        score = obj * expf(m) / sum;
    }
    u32 fs = fordf(score);
    g_keys[plane * SS + cell] =
        ((u64)fs << 32) | (u32)(~((g << 7) | (u32)am));
    if (fs > 0x80000000u) atomicAdd(&shist[(fs >> 18) - 8192u], 1u);
}

// ---------------- kernel 1: decode + scratch re-init --------------------------
__global__ void __launch_bounds__(256) k_decode(
    const float* __restrict__ o13, const float* __restrict__ o26,
    const float* __restrict__ o52)
{
    __shared__ u32 shist[HB];
    for (int i = threadIdx.x; i < HB; i += 256) shist[i] = 0;
    // replay re-init (all consumed only in k_rest, the next graph node)
    if (blockIdx.x == 0 && threadIdx.x == 0) { g_cnt = 0; g_maxfs = 0u; }
    if (blockIdx.x == 2)
        for (int i = threadIdx.x; i < NK * 6; i += 256) g_cand[i] = 0.f;
    if (blockIdx.x == 3 && threadIdx.x < NK) g_alive[threadIdx.x] = 0;
    __syncthreads();
    int item = blockIdx.x * 256 + threadIdx.x;
    if (item < WTOT) {
        if (item < W52)            decode_v4<52, G52OFF>(item, o52, shist);
        else if (item < W52 + W26) decode_v4<26, G26OFF>(item - W52, o26, shist);
        else                       decode_s13(item - (W52 + W26), o13, shist);
    }
    __syncthreads();
    for (int i = threadIdx.x; i < HB; i += 256) {
        u32 v = shist[i];
        if (v) atomicAdd(&g_hist[i], v);
    }
}

// ---------------- kernel 2: select + gather + rank/box + pairs/NMS -----------
__global__ void __launch_bounds__(BLK, 1) k_rest(
    const float* __restrict__ o13, const float* __restrict__ o26,
    const float* __restrict__ o52,
    const float* __restrict__ a13, const float* __restrict__ a26,
    const float* __restrict__ a52,
    const float* __restrict__ c1p, const float* __restrict__ c2p,
    float* __restrict__ out, int out_size)
{
    __shared__ __align__(16) unsigned char sm[45056];
    __shared__ int s_B;
    __shared__ u32 s_cnt;
    __shared__ u32 s_a0w[16], s_keep[16];

    const int tid = threadIdx.x;
    const int gt = blockIdx.x * BLK + tid;
    const int lane = tid & 31;
    const int wid = tid >> 5;

    // ===== P1: single-level select (redundant per block) + gather =====
    {
        u32* sa = (u32*)sm;
        u32* sb = sa + 1024;
        if (tid == 0) s_B = 0;
        uint4 mybins = ((const uint4*)g_hist)[tid];
        sa[tid] = mybins.x + mybins.y + mybins.z + mybins.w;
        __syncthreads();
        u32 *src = sa, *dst = sb;
        for (int off = 1; off < 1024; off <<= 1) {
            u32 v = src[tid];
            if (tid + off < 1024) v += src[tid + off];
            dst[tid] = v;
            __syncthreads();
            u32* tmp = src; src = dst; dst = tmp;
        }
        u32 run = (tid < 1023) ? src[tid + 1] : 0u;
        u32 prev;
        prev = run; run += mybins.w; if (prev < NK && run >= NK) s_B = 4 * tid + 3;
        prev = run; run += mybins.z; if (prev < NK && run >= NK) s_B = 4 * tid + 2;
        prev = run; run += mybins.y; if (prev < NK && run >= NK) s_B = 4 * tid + 1;
        prev = run; run += mybins.x; if (prev < NK && run >= NK) s_B = 4 * tid + 0;
        __syncthreads();
        u32 B = (u32)s_B;
        for (int t = gt; t < NT; t += NTH) {
            u64 k = g_keys[t];
            u32 fs = (u32)(k >> 32);
            if (fs > 0x80000000u && ((fs >> 18) - 8192u) >= B) {
                u32 pos = atomicAdd(&g_cnt, 1u);
                if (pos < (u32)CAP) g_gbuf[pos] = k;
            }
        }
    }
    grid_barrier();

    // ===== P2: warp-per-candidate rank + exact box compute + hist reset =====
    {
        if (tid == 0) s_cnt = g_cnt;
        __syncthreads();
        u32 cnt = s_cnt; if (cnt > (u32)CAP) cnt = CAP;
        if ((u32)(blockIdx.x * 32) < cnt) {
            u64* skeys = (u64*)sm;                            // 32 KB
            for (u32 i = tid; i < cnt; i += BLK) skeys[i] = g_gbuf[i];
            __syncthreads();
            u32 j = (u32)(blockIdx.x * 32 + wid);
            if (j < cnt) {
                u64 kj = skeys[j];
                int r = 0;
                for (u32 i = lane; i < cnt; i += 32) r += (int)(skeys[i] > kj);
#pragma unroll
                for (int o = 16; o > 0; o >>= 1) r += __shfl_xor_sync(0xffffffffu, r, o);
                u32 fs = (u32)(kj >> 32);
                if (r < NK && lane == 0) {                    // all gathered are positive
                    u32 v = ~(u32)kj;
                    u32 id = v >> 7;
                    int cls = (int)(v & 127u);
                    int S, a, b, cell;
                    const float *src, *anc;
                    map_id(id, o13, o26, o52, a13, a26, a52, S, src, anc, a, b, cell);
                    int SS = S * S;
                    const float* pc = src + (size_t)(b * 255 + a * 85) * SS + cell;
                    float o1 = pc[(size_t)SS],     o2 = pc[(size_t)2 * SS];
                    float o3 = pc[(size_t)3 * SS], o4 = pc[(size_t)4 * SS];
                    float c1 = *c1p, c2 = *c2p;
                    int y = cell / S, x = cell - y * S;
                    float sc = 416.f / (float)S;
                    float cx = ((float)x + o1) * sc / c1;
                    float cy = ((float)y + o2) * sc / c2;
                    float w  = expf(o3) * anc[2 * a] / c1;
                    float h  = expf(o4) * anc[2 * a + 1] / c2;
                    float p  = ifordf(fs);
                    float* cd = g_cand + r * 6;
                    cd[0] = p; cd[1] = cx; cd[2] = cy;
                    cd[3] = w; cd[4] = h; cd[5] = (float)cls;
                    g_alive[r] = 1;
                    atomicMax(&g_maxfs, fs);
                }
            }
        }
        if (blockIdx.x == GRID - 1)                           // base 4704 >= CAP: never ranks
            for (int i = tid; i < HB; i += BLK) g_hist[i] = 0;
    }
    grid_barrier();   // last barrier

    // tail-fill of out beyond 512*7 (all blocks; disjoint from block-0 writes)
    for (int i = NK * 7 + gt; i < out_size; i += NTH) out[i] = 0.f;
    if (blockIdx.x != 0) return;

    // ===== P3 (block 0): pairs in smem + alive0 + cascade + output =====
    {
        u32*   ssup  = (u32*)sm;                 // 32 KB
        float* scand = (float*)(sm + 32768);     // 12 KB
        float maxp = (g_maxfs > 0x80000000u) ? ifordf(g_maxfs) : 0.f;
        for (int i = tid; i < NK * 6; i += BLK) scand[i] = g_cand[i];
        if (tid < NK) {
            bool a0 = (g_alive[tid] != 0) && (g_cand[tid * 6] > 0.5f * maxp);
            u32 m = __ballot_sync(0xffffffffu, a0);
            if (lane == 0) s_a0w[tid >> 5] = m;
        }
        __syncthreads();

        // warp per row (32 warps x 16 rows each): full 512x512 suppress bitmask
        for (int row = wid; row < NK; row += 32) {
            const float* bI = scand + row * 6;
            float x1i = bI[1] - bI[3] * 0.5f, y1i = bI[2] - bI[4] * 0.5f;
            float x2i = x1i + bI[3],          y2i = y1i + bI[4];
            float ai = (x2i - x1i) * (y2i - y1i);
            float cli = bI[5];
#pragma unroll 4
            for (int cw = 0; cw < 16; ++cw) {
                int col = (cw << 5) + lane;
                const float* bj = scand + col * 6;
                float wj = bj[3], hj = bj[4];
                float x1j = bj[1] - wj * 0.5f, y1j = bj[2] - hj * 0.5f;
                float x2j = x1j + wj,          y2j = y1j + hj;
                float iw = fmaxf(fminf(x2i, x2j) - fmaxf(x1i, x1j), 0.f);
                float ih = fmaxf(fminf(y2i, y2j) - fmaxf(y1i, y1j), 0.f);
                float inter = iw * ih;
                float aj = (x2j - x1j) * (y2j - y1j);
                float iou = inter / (ai + aj - inter);
                bool sup = (cli == bj[5]) || (iou >= 0.5f);
                u32 m = __ballot_sync(0xffffffffu, sup);
                if (lane == 0) ssup[row * 16 + cw] = m;
            }
        }
        __syncthreads();

        if (tid == 0) {
            u32 sup[16], keep[16];
#pragma unroll
            for (int x = 0; x < 16; ++x) { sup[x] = ~s_a0w[x]; keep[x] = 0u; }
            for (int w = 0; w < 16; ++w) {
                u32 avail = ~sup[w];
                while (avail) {
                    int bb = __ffs(avail) - 1;
                    int i = (w << 5) + bb;
                    keep[w] |= (1u << bb);
#pragma unroll
                    for (int x = 0; x < 16; ++x) sup[x] |= ssup[i * 16 + x];
                    u32 hi = (bb == 31) ? 0u : (0xffffffffu << (bb + 1));
                    avail = ~sup[w] & hi;
                }
            }
#pragma unroll
            for (int x = 0; x < 16; ++x) s_keep[x] = keep[x];
        }
        __syncthreads();

        if (tid < NK) {
            bool kp = (s_keep[tid >> 5] >> (tid & 31)) & 1u;
            float km = kp ? 1.f : 0.f;
            if (out_size >= NK * 6) {
#pragma unroll
                for (int c = 0; c < 6; ++c) out[tid * 6 + c] = scand[tid * 6 + c] * km;
            }
            if (out_size >= NK * 7) out[NK * 6 + tid] = km;
        }
    }
}

// ---------------- launch: TWO kernels ------------------------------------------
extern "C" void kernel_launch(void* const* d_in, const int* in_sizes, int n_in,
                              void* d_out, int out_size) {
    k_decode<<<(WTOT + 255) / 256, 256>>>(
        (const float*)d_in[0], (const float*)d_in[1], (const float*)d_in[2]);
    k_rest<<<GRID, BLK>>>(
        (const float*)d_in[0], (const float*)d_in[1], (const float*)d_in[2],
        (const float*)d_in[3], (const float*)d_in[4], (const float*)d_in[5],
        (const float*)d_in[6], (const float*)d_in[7],
        (float*)d_out, out_size);
}

// round 13
// speedup vs baseline: 2.3416x; 2.3416x over previous
#include <cuda_runtime.h>
#include <cstdint>

typedef unsigned long long u64;
typedef unsigned u32;

#define N13   16224
#define N26   64896
#define N52   259584
#define NT    340704
#define CAP   4096
#define NK    512
#define HB    4096
#define GRID  148
#define BLK   1024
#define NTH   (GRID*BLK)

#define G26OFF 16224
#define G52OFF 81120

#define W52 64896
#define W26 16224
#define W13 16224
#define WTOT 97344

// ---------------- scratch (static device globals: no allocation) ------------
__device__ u64   g_keys[NT];
__device__ u32   g_hist[HB];
__device__ u32   g_cnt;
__device__ u32   g_maxfs;
__device__ u64   g_gbuf[CAP];
__device__ float g_cand[NK * 6];
__device__ unsigned char g_alive[NK];
__device__ u32   g_sup[NK * 16];
__device__ u32   g_bar_arrive;
__device__ u32   g_bar_gen;

__device__ __forceinline__ u32 fordf(float f) {
    u32 u = __float_as_uint(f);
    return (u & 0x80000000u) ? ~u : (u | 0x80000000u);
}
__device__ __forceinline__ float ifordf(u32 e) {
    return __uint_as_float((e & 0x80000000u) ? (e & 0x7fffffffu) : ~e);
}

// grid barrier: exactly one block per SM (GRID=148, launch_bounds(1024,1))
__device__ __forceinline__ void grid_barrier() {
    __syncthreads();
    __threadfence();
    if (threadIdx.x == 0) {
        volatile u32* vgen = &g_bar_gen;
        u32 gen = *vgen;
        __threadfence();
        u32 a = atomicAdd(&g_bar_arrive, 1u);
        if (a == GRID - 1u) {
            g_bar_arrive = 0u;
            __threadfence();
            atomicAdd(&g_bar_gen, 1u);
        } else {
            while (*vgen == gen) {}
        }
    }
    __threadfence();
    __syncthreads();
}

// map candidate id -> (S, src, anc, a, b, cell)
__device__ __forceinline__ void map_id(u32 id,
    const float* o13, const float* o26, const float* o52,
    const float* a13, const float* a26, const float* a52,
    int& S, const float*& src, const float*& anc, int& a, int& b, int& cell) {
    u32 rid = id;
    if (id < N13)            { S = 13; src = o13; anc = a13; }
    else if (id < N13 + N26) { S = 26; src = o26; anc = a26; rid = id - N13; }
    else                     { S = 52; src = o52; anc = a52; rid = id - (N13 + N26); }
    a = rid % 3;
    u32 q = rid / 3;
    int SS = S * S;
    b = q / SS;
    cell = q - b * SS;
}

// ---------------- decode: score-only, vec4, precise expf, streaming ----------
template <int S, int GOFF>
__device__ __forceinline__ void decode_v4(int v,
                                          const float* __restrict__ out,
                                          u32* shist) {
    const int SS = S * S, G4 = SS / 4;
    int plane = v / G4;
    int grp = v - plane * G4;
    int cell0 = grp * 4;
    int b = plane / 3, a = plane - 3 * b;
    const float* pc = out + ((size_t)b * 255 + (size_t)a * 85) * SS + cell0;
    float4 q0 = __ldcs((const float4*)pc);
    float m0 = -1e30f, m1 = -1e30f, m2 = -1e30f, m3 = -1e30f;
    float s0 = 0.f, s1 = 0.f, s2 = 0.f, s3 = 0.f;
    int i0 = 0, i1 = 0, i2 = 0, i3 = 0;
#pragma unroll 4
    for (int c = 0; c < 80; ++c) {
        float4 l = __ldcs((const float4*)(pc + (size_t)(5 + c) * SS));
        s0 += expf(l.x); if (l.x > m0) { m0 = l.x; i0 = c; }
        s1 += expf(l.y); if (l.y > m1) { m1 = l.y; i1 = c; }
        s2 += expf(l.z); if (l.z > m2) { m2 = l.z; i2 = c; }
        s3 += expf(l.w); if (l.w > m3) { m3 = l.w; i3 = c; }
    }
    float o0a[4] = {q0.x, q0.y, q0.z, q0.w};
    float ma[4] = {m0, m1, m2, m3};
    float sa[4] = {s0, s1, s2, s3};
    int   ia[4] = {i0, i1, i2, i3};
#pragma unroll
    for (int k = 0; k < 4; ++k) {
        int cell = cell0 + k;
        u32 g = (u32)(GOFF + (b * SS + cell) * 3 + a);
        float score = -1.f;
        if (o0a[k] > 0.f) {
            float obj = 1.f / (1.f + expf(-o0a[k]));
            score = obj * expf(ma[k]) / sa[k];
        }
        u32 fs = fordf(score);
        g_keys[GOFF + plane * SS + cell] =
            ((u64)fs << 32) | (u32)(~((g << 7) | (u32)ia[k]));
        if (fs > 0x80000000u) atomicAdd(&shist[(fs >> 18) - 8192u], 1u);
    }
}

__device__ __forceinline__ void decode_s13(int v,
                                           const float* __restrict__ out,
                                           u32* shist) {
    const int S = 13, SS = 169;
    int plane = v / SS;
    int cell = v - plane * SS;
    int b = plane / 3, a = plane - 3 * b;
    const float* pc = out + ((size_t)b * 255 + (size_t)a * 85) * SS + cell;
    float o0 = __ldcs(pc);
    u32 g = (u32)((b * SS + cell) * 3 + a);
    float score = -1.f;
    float m = -1e30f, sum = 0.f; int am = 0;
#pragma unroll 4
    for (int c = 0; c < 80; ++c) {
        float l = __ldcs(pc + (size_t)(5 + c) * SS);
        sum += expf(l);
        if (l > m) { m = l; am = c; }
    }
    if (o0 > 0.f) {
        float obj = 1.f / (1.f + expf(-o0));
        score = obj * expf(m) / sum;
    }
    u32 fs = fordf(score);
    g_keys[plane * SS + cell] =
        ((u64)fs << 32) | (u32)(~((g << 7) | (u32)am));
    if (fs > 0x80000000u) atomicAdd(&shist[(fs >> 18) - 8192u], 1u);
}

// ---------------- kernel 1: decode + scratch re-init --------------------------
__global__ void __launch_bounds__(256) k_decode(
    const float* __restrict__ o13, const float* __restrict__ o26,
    const float* __restrict__ o52)
{
    __shared__ u32 shist[HB];
    for (int i = threadIdx.x; i < HB; i += 256) shist[i] = 0;
    // replay re-init (all consumed only in k_rest, the next graph node)
    if (blockIdx.x == 0 && threadIdx.x == 0) { g_cnt = 0; g_maxfs = 0u; }
    if (blockIdx.x == 2)
        for (int i = threadIdx.x; i < NK * 6; i += 256) g_cand[i] = 0.f;
    if (blockIdx.x == 3 && threadIdx.x < NK) g_alive[threadIdx.x] = 0;
    __syncthreads();
    int item = blockIdx.x * 256 + threadIdx.x;
    if (item < WTOT) {
        if (item < W52)            decode_v4<52, G52OFF>(item, o52, shist);
        else if (item < W52 + W26) decode_v4<26, G26OFF>(item - W52, o26, shist);
        else                       decode_s13(item - (W52 + W26), o13, shist);
    }
    __syncthreads();
    for (int i = threadIdx.x; i < HB; i += 256) {
        u32 v = shist[i];
        if (v) atomicAdd(&g_hist[i], v);
    }
}

// ---------------- kernel 2: select + gather + rank/box + pairs + NMS ---------
__global__ void __launch_bounds__(BLK, 1) k_rest(
    const float* __restrict__ o13, const float* __restrict__ o26,
    const float* __restrict__ o52,
    const float* __restrict__ a13, const float* __restrict__ a26,
    const float* __restrict__ a52,
    const float* __restrict__ c1p, const float* __restrict__ c2p,
    float* __restrict__ out, int out_size)
{
    __shared__ __align__(16) unsigned char sm[45056];
    __shared__ int s_B;
    __shared__ u32 s_cnt;
    __shared__ u32 s_a0w[16], s_keep[16];

    const int tid = threadIdx.x;
    const int gt = blockIdx.x * BLK + tid;
    const int lane = tid & 31;
    const int wid = tid >> 5;

    // ===== P1: single-level select (redundant per block) + gather =====
    {
        u32* sa = (u32*)sm;
        u32* sb = sa + 1024;
        if (tid == 0) s_B = 0;
        uint4 mybins = ((const uint4*)g_hist)[tid];
        sa[tid] = mybins.x + mybins.y + mybins.z + mybins.w;
        __syncthreads();
        u32 *src = sa, *dst = sb;
        for (int off = 1; off < 1024; off <<= 1) {
            u32 v = src[tid];
            if (tid + off < 1024) v += src[tid + off];
            dst[tid] = v;
            __syncthreads();
            u32* tmp = src; src = dst; dst = tmp;
        }
        u32 run = (tid < 1023) ? src[tid + 1] : 0u;
        u32 prev;
        prev = run; run += mybins.w; if (prev < NK && run >= NK) s_B = 4 * tid + 3;
        prev = run; run += mybins.z; if (prev < NK && run >= NK) s_B = 4 * tid + 2;
        prev = run; run += mybins.y; if (prev < NK && run >= NK) s_B = 4 * tid + 1;
        prev = run; run += mybins.x; if (prev < NK && run >= NK) s_B = 4 * tid + 0;
        __syncthreads();
        u32 B = (u32)s_B;
        for (int t = gt; t < NT; t += NTH) {
            u64 k = g_keys[t];
            u32 fs = (u32)(k >> 32);
            if (fs > 0x80000000u && ((fs >> 18) - 8192u) >= B) {
                u32 pos = atomicAdd(&g_cnt, 1u);
                if (pos < (u32)CAP) g_gbuf[pos] = k;
            }
        }
    }
    grid_barrier();

    // ===== P2: warp-per-candidate rank + exact box compute + hist reset =====
    {
        if (tid == 0) s_cnt = g_cnt;
        __syncthreads();
        u32 cnt = s_cnt; if (cnt > (u32)CAP) cnt = CAP;
        if ((u32)(blockIdx.x * 32) < cnt) {
            u64* skeys = (u64*)sm;                            // 32 KB
            for (u32 i = tid; i < cnt; i += BLK) skeys[i] = g_gbuf[i];
            __syncthreads();
            u32 j = (u32)(blockIdx.x * 32 + wid);
            if (j < cnt) {
                u64 kj = skeys[j];
                int r = 0;
                for (u32 i = lane; i < cnt; i += 32) r += (int)(skeys[i] > kj);
#pragma unroll
                for (int o = 16; o > 0; o >>= 1) r += __shfl_xor_sync(0xffffffffu, r, o);
                u32 fs = (u32)(kj >> 32);
                if (r < NK && lane == 0) {                    // all gathered are positive
                    u32 v = ~(u32)kj;
                    u32 id = v >> 7;
                    int cls = (int)(v & 127u);
                    int S, a, b, cell;
                    const float *src, *anc;
                    map_id(id, o13, o26, o52, a13, a26, a52, S, src, anc, a, b, cell);
                    int SS = S * S;
                    const float* pc = src + (size_t)(b * 255 + a * 85) * SS + cell;
                    float o1 = pc[(size_t)SS],     o2 = pc[(size_t)2 * SS];
                    float o3 = pc[(size_t)3 * SS], o4 = pc[(size_t)4 * SS];
                    float c1 = *c1p, c2 = *c2p;
                    int y = cell / S, x = cell - y * S;
                    float sc = 416.f / (float)S;
                    float cx = ((float)x + o1) * sc / c1;
                    float cy = ((float)y + o2) * sc / c2;
                    float w  = expf(o3) * anc[2 * a] / c1;
                    float h  = expf(o4) * anc[2 * a + 1] / c2;
                    float p  = ifordf(fs);
                    float* cd = g_cand + r * 6;
                    cd[0] = p; cd[1] = cx; cd[2] = cy;
                    cd[3] = w; cd[4] = h; cd[5] = (float)cls;
                    g_alive[r] = 1;
                    atomicMax(&g_maxfs, fs);
                }
            }
        }
        if (blockIdx.x == GRID - 1)                           // base 4704 >= CAP: never ranks
            for (int i = tid; i < HB; i += BLK) g_hist[i] = 0;
    }
    grid_barrier();

    // ===== P3: parallel pairwise suppress bitmask (distributed, global bj) ====
    {
        __shared__ float bi[2][6];
        int half = tid >> 9;
        int col  = tid & 511;
        for (int row0 = blockIdx.x * 2; row0 < NK; row0 += GRID * 2) {
            int row = row0 + half;
            if (tid < 12) bi[tid / 6][tid % 6] = g_cand[(row0 + tid / 6) * 6 + tid % 6];
            __syncthreads();
            {
                const float* bI = bi[half];
                const float* bj = g_cand + col * 6;
                float x1i = bI[1] - bI[3] * 0.5f, y1i = bI[2] - bI[4] * 0.5f;
                float x2i = x1i + bI[3],          y2i = y1i + bI[4];
                float x1j = bj[1] - bj[3] * 0.5f, y1j = bj[2] - bj[4] * 0.5f;
                float x2j = x1j + bj[3],          y2j = y1j + bj[4];
                float iw = fmaxf(fminf(x2i, x2j) - fmaxf(x1i, x1j), 0.f);
                float ih = fmaxf(fminf(y2i, y2j) - fmaxf(y1i, y1j), 0.f);
                float inter = iw * ih;
                float ai = (x2i - x1i) * (y2i - y1i);
                float aj = (x2j - x1j) * (y2j - y1j);
                float iou = inter / (ai + aj - inter);
                bool sup = (bI[5] == bj[5]) || (iou >= 0.5f);
                u32 m = __ballot_sync(0xffffffffu, sup);
                if (lane == 0) g_sup[row * 16 + (col >> 5)] = m;
            }
            __syncthreads();
        }
    }
    grid_barrier();   // last barrier

    // tail-fill of out beyond 512*7 (all blocks; disjoint from block-0 writes)
    for (int i = NK * 7 + gt; i < out_size; i += NTH) out[i] = 0.f;
    if (blockIdx.x != 0) return;

    // ===== P4 (block 0): alive0 + serial cascade + output =====
    {
        u32*   ssup  = (u32*)sm;                 // 32 KB
        float* scand = (float*)(sm + 32768);     // 12 KB
        float maxp = (g_maxfs > 0x80000000u) ? ifordf(g_maxfs) : 0.f;
        for (int i = tid; i < NK * 16; i += BLK) ssup[i] = g_sup[i];
        for (int i = tid; i < NK * 6;  i += BLK) scand[i] = g_cand[i];
        if (tid < NK) {
            bool a0 = (g_alive[tid] != 0) && (g_cand[tid * 6] > 0.5f * maxp);
            u32 m = __ballot_sync(0xffffffffu, a0);
            if (lane == 0) s_a0w[tid >> 5] = m;
        }
        __syncthreads();

        if (tid == 0) {
            u32 sup[16], keep[16];
#pragma unroll
            for (int x = 0; x < 16; ++x) { sup[x] = ~s_a0w[x]; keep[x] = 0u; }
            for (int w = 0; w < 16; ++w) {
                u32 avail = ~sup[w];
                while (avail) {
                    int bb = __ffs(avail) - 1;
                    int i = (w << 5) + bb;
                    keep[w] |= (1u << bb);
#pragma unroll
                    for (int x = 0; x < 16; ++x) sup[x] |= ssup[i * 16 + x];
                    u32 hi = (bb == 31) ? 0u : (0xffffffffu << (bb + 1));
                    avail = ~sup[w] & hi;
                }
            }
#pragma unroll
            for (int x = 0; x < 16; ++x) s_keep[x] = keep[x];
        }
        __syncthreads();

        if (tid < NK) {
            bool kp = (s_keep[tid >> 5] >> (tid & 31)) & 1u;
            float km = kp ? 1.f : 0.f;
            if (out_size >= NK * 6) {
#pragma unroll
                for (int c = 0; c < 6; ++c) out[tid * 6 + c] = scand[tid * 6 + c] * km;
            }
            if (out_size >= NK * 7) out[NK * 6 + tid] = km;
        }
    }
}

// ---------------- launch: TWO kernels ------------------------------------------
extern "C" void kernel_launch(void* const* d_in, const int* in_sizes, int n_in,
                              void* d_out, int out_size) {
    k_decode<<<(WTOT + 255) / 256, 256>>>(
        (const float*)d_in[0], (const float*)d_in[1], (const float*)d_in[2]);
    k_rest<<<GRID, BLK>>>(
        (const float*)d_in[0], (const float*)d_in[1], (const float*)d_in[2],
        (const float*)d_in[3], (const float*)d_in[4], (const float*)d_in[5],
        (const float*)d_in[6], (const float*)d_in[7],
        (float*)d_out, out_size);
}

// round 14
// speedup vs baseline: 2.5708x; 1.0979x over previous
#include <cuda_runtime.h>
#include <cstdint>

typedef unsigned long long u64;
typedef unsigned u32;

#define N13   16224
#define N26   64896
#define N52   259584
#define NT    340704
#define CAP   4096
#define NK    512
#define HB    4096
#define GRID  148
#define BLK   1024
#define NTH   (GRID*BLK)

#define G26OFF 16224
#define G52OFF 81120

#define W52V2 129792          // vec2 items for scale 52 (259584/2)
#define W26V2 32448           // vec2 items for scale 26 (64896/2)
#define W13   16224           // scalar items for scale 13
#define WTOT2 178464

// ---------------- scratch (static device globals: no allocation) ------------
__device__ u64   g_keys[NT];
__device__ u32   g_hist[HB];
__device__ u32   g_cnt;
__device__ u32   g_maxfs;
__device__ u64   g_gbuf[CAP];
__device__ float g_cand[NK * 6];
__device__ unsigned char g_alive[NK];
__device__ u32   g_sup[NK * 16];
__device__ u32   g_bar_arrive;
__device__ u32   g_bar_gen;

__device__ __forceinline__ u32 fordf(float f) {
    u32 u = __float_as_uint(f);
    return (u & 0x80000000u) ? ~u : (u | 0x80000000u);
}
__device__ __forceinline__ float ifordf(u32 e) {
    return __uint_as_float((e & 0x80000000u) ? (e & 0x7fffffffu) : ~e);
}

// grid barrier: exactly one block per SM (GRID=148, launch_bounds(1024,1))
__device__ __forceinline__ void grid_barrier() {
    __syncthreads();
    __threadfence();
    if (threadIdx.x == 0) {
        volatile u32* vgen = &g_bar_gen;
        u32 gen = *vgen;
        __threadfence();
        u32 a = atomicAdd(&g_bar_arrive, 1u);
        if (a == GRID - 1u) {
            g_bar_arrive = 0u;
            __threadfence();
            atomicAdd(&g_bar_gen, 1u);
        } else {
            while (*vgen == gen) {}
        }
    }
    __threadfence();
    __syncthreads();
}

// map candidate id -> (S, src, anc, a, b, cell)
__device__ __forceinline__ void map_id(u32 id,
    const float* o13, const float* o26, const float* o52,
    const float* a13, const float* a26, const float* a52,
    int& S, const float*& src, const float*& anc, int& a, int& b, int& cell) {
    u32 rid = id;
    if (id < N13)            { S = 13; src = o13; anc = a13; }
    else if (id < N13 + N26) { S = 26; src = o26; anc = a26; rid = id - N13; }
    else                     { S = 52; src = o52; anc = a52; rid = id - (N13 + N26); }
    a = rid % 3;
    u32 q = rid / 3;
    int SS = S * S;
    b = q / SS;
    cell = q - b * SS;
}

// ---------------- decode: score-only, vec2 (occupancy), precise expf ---------
template <int S, int GOFF>
__device__ __forceinline__ void decode_v2(int v,
                                          const float* __restrict__ out,
                                          u32* shist) {
    const int SS = S * S, G2 = SS / 2;
    int plane = v / G2;
    int grp = v - plane * G2;
    int cell0 = grp * 2;
    int b = plane / 3, a = plane - 3 * b;
    const float* pc = out + ((size_t)(b * 255 + a * 85)) * SS + cell0;
    float2 q0 = __ldcs((const float2*)pc);
    float m0 = -1e30f, m1 = -1e30f;
    float s0 = 0.f, s1 = 0.f;
    int i0 = 0, i1 = 0;
#pragma unroll 8
    for (int c = 0; c < 80; ++c) {
        float2 l = __ldcs((const float2*)(pc + (size_t)(5 + c) * SS));
        s0 += expf(l.x); if (l.x > m0) { m0 = l.x; i0 = c; }
        s1 += expf(l.y); if (l.y > m1) { m1 = l.y; i1 = c; }
    }
    float o0a[2] = {q0.x, q0.y};
    float ma[2] = {m0, m1};
    float sa[2] = {s0, s1};
    int   ia[2] = {i0, i1};
#pragma unroll
    for (int k = 0; k < 2; ++k) {
        int cell = cell0 + k;
        u32 g = (u32)(GOFF + (b * SS + cell) * 3 + a);
        float score = -1.f;
        if (o0a[k] > 0.f) {
            float obj = 1.f / (1.f + expf(-o0a[k]));
            score = obj * expf(ma[k]) / sa[k];
        }
        u32 fs = fordf(score);
        g_keys[GOFF + plane * SS + cell] =
            ((u64)fs << 32) | (u32)(~((g << 7) | (u32)ia[k]));
        if (fs > 0x80000000u) atomicAdd(&shist[(fs >> 18) - 8192u], 1u);
    }
}

__device__ __forceinline__ void decode_s13(int v,
                                           const float* __restrict__ out,
                                           u32* shist) {
    const int S = 13, SS = 169;
    int plane = v / SS;
    int cell = v - plane * SS;
    int b = plane / 3, a = plane - 3 * b;
    const float* pc = out + ((size_t)(b * 255 + a * 85)) * SS + cell;
    float o0 = __ldcs(pc);
    u32 g = (u32)((b * SS + cell) * 3 + a);
    float score = -1.f;
    float m = -1e30f, sum = 0.f; int am = 0;
#pragma unroll 4
    for (int c = 0; c < 80; ++c) {
        float l = __ldcs(pc + (size_t)(5 + c) * SS);
        sum += expf(l);
        if (l > m) { m = l; am = c; }
    }
    if (o0 > 0.f) {
        float obj = 1.f / (1.f + expf(-o0));
        score = obj * expf(m) / sum;
    }
    u32 fs = fordf(score);
    g_keys[plane * SS + cell] =
        ((u64)fs << 32) | (u32)(~((g << 7) | (u32)am));
    if (fs > 0x80000000u) atomicAdd(&shist[(fs >> 18) - 8192u], 1u);
}

// ---------------- kernel 1: decode + scratch re-init --------------------------
__global__ void __launch_bounds__(256) k_decode(
    const float* __restrict__ o13, const float* __restrict__ o26,
    const float* __restrict__ o52)
{
    __shared__ u32 shist[HB];
    for (int i = threadIdx.x; i < HB; i += 256) shist[i] = 0;
    // replay re-init (all consumed only in k_rest, the next graph node)
    if (blockIdx.x == 0 && threadIdx.x == 0) { g_cnt = 0; g_maxfs = 0u; }
    if (blockIdx.x == 2)
        for (int i = threadIdx.x; i < NK * 6; i += 256) g_cand[i] = 0.f;
    if (blockIdx.x == 3 && threadIdx.x < NK) g_alive[threadIdx.x] = 0;
    __syncthreads();
    int item = blockIdx.x * 256 + threadIdx.x;
    if (item < WTOT2) {
        if (item < W52V2)              decode_v2<52, G52OFF>(item, o52, shist);
        else if (item < W52V2 + W26V2) decode_v2<26, G26OFF>(item - W52V2, o26, shist);
        else                           decode_s13(item - (W52V2 + W26V2), o13, shist);
    }
    __syncthreads();
    for (int i = threadIdx.x; i < HB; i += 256) {
        u32 v = shist[i];
        if (v) atomicAdd(&g_hist[i], v);
    }
}

// ---------------- kernel 2: select + gather + rank/box + pairs + NMS ---------
__global__ void __launch_bounds__(BLK, 1) k_rest(
    const float* __restrict__ o13, const float* __restrict__ o26,
    const float* __restrict__ o52,
    const float* __restrict__ a13, const float* __restrict__ a26,
    const float* __restrict__ a52,
    const float* __restrict__ c1p, const float* __restrict__ c2p,
    float* __restrict__ out, int out_size)
{
    __shared__ __align__(16) unsigned char sm[45056];
    __shared__ int s_B;
    __shared__ u32 s_cnt;
    __shared__ u32 s_a0w[16], s_keep[16];
    __shared__ u32 s_wtot[32], s_wsuf[32];

    const int tid = threadIdx.x;
    const int gt = blockIdx.x * BLK + tid;
    const int lane = tid & 31;
    const int wid = tid >> 5;

    // ===== P1: single-level select (warp-shfl suffix scan) + gather =====
    {
        if (tid == 0) s_B = 0;
        uint4 mybins = ((const uint4*)g_hist)[tid];           // bins [4t, 4t+4)
        u32 p = mybins.x + mybins.y + mybins.z + mybins.w;
        u32 v = p;                                            // inclusive suffix in-warp
#pragma unroll
        for (int off = 1; off < 32; off <<= 1) {
            u32 t = __shfl_down_sync(0xffffffffu, v, off);
            if (lane + off < 32) v += t;
        }
        if (lane == 0) s_wtot[wid] = v;                       // warp total
        __syncthreads();
        if (wid == 0) {
            u32 wv = s_wtot[lane];
            u32 iv = wv;
#pragma unroll
            for (int off = 1; off < 32; off <<= 1) {
                u32 t = __shfl_down_sync(0xffffffffu, iv, off);
                if (lane + off < 32) iv += t;
            }
            s_wsuf[lane] = iv - wv;                           // exclusive suffix of warps above
        }
        __syncthreads();
        u32 run = (v - p) + s_wsuf[wid];                      // suffix strictly above my 4 bins
        u32 prev;
        prev = run; run += mybins.w; if (prev < NK && run >= NK) s_B = 4 * tid + 3;
        prev = run; run += mybins.z; if (prev < NK && run >= NK) s_B = 4 * tid + 2;
        prev = run; run += mybins.y; if (prev < NK && run >= NK) s_B = 4 * tid + 1;
        prev = run; run += mybins.x; if (prev < NK && run >= NK) s_B = 4 * tid + 0;
        __syncthreads();
        u32 B = (u32)s_B;
        for (int t = gt; t < NT; t += NTH) {
            u64 k = g_keys[t];
            u32 fs = (u32)(k >> 32);
            if (fs > 0x80000000u && ((fs >> 18) - 8192u) >= B) {
                u32 pos = atomicAdd(&g_cnt, 1u);
                if (pos < (u32)CAP) g_gbuf[pos] = k;
            }
        }
    }
    grid_barrier();

    // ===== P2: warp-per-candidate rank + exact box compute + hist reset =====
    {
        if (tid == 0) s_cnt = g_cnt;
        __syncthreads();
        u32 cnt = s_cnt; if (cnt > (u32)CAP) cnt = CAP;
        if ((u32)(blockIdx.x * 32) < cnt) {
            u64* skeys = (u64*)sm;                            // 32 KB
            for (u32 i = tid; i < cnt; i += BLK) skeys[i] = g_gbuf[i];
            __syncthreads();
            u32 j = (u32)(blockIdx.x * 32 + wid);
            if (j < cnt) {
                u64 kj = skeys[j];
                int r = 0;
                for (u32 i = lane; i < cnt; i += 32) r += (int)(skeys[i] > kj);
#pragma unroll
                for (int o = 16; o > 0; o >>= 1) r += __shfl_xor_sync(0xffffffffu, r, o);
                u32 fs = (u32)(kj >> 32);
                if (r < NK && lane == 0) {                    // all gathered are positive
                    u32 v = ~(u32)kj;
                    u32 id = v >> 7;
                    int cls = (int)(v & 127u);
                    int S, a, b, cell;
                    const float *src, *anc;
                    map_id(id, o13, o26, o52, a13, a26, a52, S, src, anc, a, b, cell);
                    int SS = S * S;
                    const float* pc = src + (size_t)(b * 255 + a * 85) * SS + cell;
                    float o1 = pc[(size_t)SS],     o2 = pc[(size_t)2 * SS];
                    float o3 = pc[(size_t)3 * SS], o4 = pc[(size_t)4 * SS];
                    float c1 = *c1p, c2 = *c2p;
                    int y = cell / S, x = cell - y * S;
                    float sc = 416.f / (float)S;
                    float cx = ((float)x + o1) * sc / c1;
                    float cy = ((float)y + o2) * sc / c2;
                    float w  = expf(o3) * anc[2 * a] / c1;
                    float h  = expf(o4) * anc[2 * a + 1] / c2;
                    float p  = ifordf(fs);
                    float* cd = g_cand + r * 6;
                    cd[0] = p; cd[1] = cx; cd[2] = cy;
                    cd[3] = w; cd[4] = h; cd[5] = (float)cls;
                    g_alive[r] = 1;
                    atomicMax(&g_maxfs, fs);
                }
            }
        }
        if (blockIdx.x == GRID - 1)                           // base 4704 >= CAP: never ranks
            for (int i = tid; i < HB; i += BLK) g_hist[i] = 0;
    }
    grid_barrier();

    // ===== P3: parallel pairwise suppress bitmask (distributed, global bj) ====
    {
        __shared__ float bi[2][6];
        int half = tid >> 9;
        int col  = tid & 511;
        for (int row0 = blockIdx.x * 2; row0 < NK; row0 += GRID * 2) {
            int row = row0 + half;
            if (tid < 12) bi[tid / 6][tid % 6] = g_cand[(row0 + tid / 6) * 6 + tid % 6];
            __syncthreads();
            {
                const float* bI = bi[half];
                const float* bj = g_cand + col * 6;
                float x1i = bI[1] - bI[3] * 0.5f, y1i = bI[2] - bI[4] * 0.5f;
                float x2i = x1i + bI[3],          y2i = y1i + bI[4];
                float x1j = bj[1] - bj[3] * 0.5f, y1j = bj[2] - bj[4] * 0.5f;
                float x2j = x1j + bj[3],          y2j = y1j + bj[4];
                float iw = fmaxf(fminf(x2i, x2j) - fmaxf(x1i, x1j), 0.f);
                float ih = fmaxf(fminf(y2i, y2j) - fmaxf(y1i, y1j), 0.f);
                float inter = iw * ih;
                float ai = (x2i - x1i) * (y2i - y1i);
                float aj = (x2j - x1j) * (y2j - y1j);
                float iou = inter / (ai + aj - inter);
                bool sup = (bI[5] == bj[5]) || (iou >= 0.5f);
                u32 m = __ballot_sync(0xffffffffu, sup);
                if (lane == 0) g_sup[row * 16 + (col >> 5)] = m;
            }
            __syncthreads();
        }
    }
    grid_barrier();   // last barrier

    // tail-fill of out beyond 512*7 (all blocks; disjoint from block-0 writes)
    for (int i = NK * 7 + gt; i < out_size; i += NTH) out[i] = 0.f;
    if (blockIdx.x != 0) return;

    // ===== P4 (block 0): alive0 + serial cascade + output =====
    {
        u32*   ssup  = (u32*)sm;                 // 32 KB
        float* scand = (float*)(sm + 32768);     // 12 KB
        float maxp = (g_maxfs > 0x80000000u) ? ifordf(g_maxfs) : 0.f;
        for (int i = tid; i < NK * 16; i += BLK) ssup[i] = g_sup[i];
        for (int i = tid; i < NK * 6;  i += BLK) scand[i] = g_cand[i];
        if (tid < NK) {
            bool a0 = (g_alive[tid] != 0) && (g_cand[tid * 6] > 0.5f * maxp);
            u32 m = __ballot_sync(0xffffffffu, a0);
            if (lane == 0) s_a0w[tid >> 5] = m;
        }
        __syncthreads();

        if (tid == 0) {
            u32 sup[16], keep[16];
#pragma unroll
            for (int x = 0; x < 16; ++x) { sup[x] = ~s_a0w[x]; keep[x] = 0u; }
            for (int w = 0; w < 16; ++w) {
                u32 avail = ~sup[w];
                while (avail) {
                    int bb = __ffs(avail) - 1;
                    int i = (w << 5) + bb;
                    keep[w] |= (1u << bb);
#pragma unroll
                    for (int x = 0; x < 16; ++x) sup[x] |= ssup[i * 16 + x];
                    u32 hi = (bb == 31) ? 0u : (0xffffffffu << (bb + 1));
                    avail = ~sup[w] & hi;
                }
            }
#pragma unroll
            for (int x = 0; x < 16; ++x) s_keep[x] = keep[x];
        }
        __syncthreads();

        if (tid < NK) {
            bool kp = (s_keep[tid >> 5] >> (tid & 31)) & 1u;
            float km = kp ? 1.f : 0.f;
            if (out_size >= NK * 6) {
#pragma unroll
                for (int c = 0; c < 6; ++c) out[tid * 6 + c] = scand[tid * 6 + c] * km;
            }
            if (out_size >= NK * 7) out[NK * 6 + tid] = km;
        }
    }
}

// ---------------- launch: TWO kernels ------------------------------------------
extern "C" void kernel_launch(void* const* d_in, const int* in_sizes, int n_in,
                              void* d_out, int out_size) {
    k_decode<<<(WTOT2 + 255) / 256, 256>>>(
        (const float*)d_in[0], (const float*)d_in[1], (const float*)d_in[2]);
    k_rest<<<GRID, BLK>>>(
        (const float*)d_in[0], (const float*)d_in[1], (const float*)d_in[2],
        (const float*)d_in[3], (const float*)d_in[4], (const float*)d_in[5],
        (const float*)d_in[6], (const float*)d_in[7],
        (float*)d_out, out_size);
}